// round 2
// baseline (speedup 1.0000x reference)
#include <cuda_runtime.h>
#include <math.h>

#define BB 2
#define SS 2048
#define DD 2048
#define HH 16
#define DHH 128
#define ND3 (3*DD)

// ---------------- scratch (static device globals; no allocation) ----------------
__device__ float g_qkv[(size_t)BB*SS*ND3];      // [B,S,3D]   ~100MB
__device__ float g_q  [(size_t)BB*HH*SS*DHH];   // [B,H,S,DH] ~33MB (pre-scaled by 1/sqrt(DH))
__device__ float g_k  [(size_t)BB*HH*SS*DHH];
__device__ float g_v  [(size_t)BB*HH*SS*DHH];
__device__ float g_ctx[(size_t)BB*SS*DD];       // [B,S,H*DH] ~67MB
__device__ float g_cos[SS*64];
__device__ float g_sin[SS*64];

// ---------------- RoPE tables (double trig for accuracy) ----------------
__global__ void rope_table_kernel() {
    int idx = blockIdx.x * blockDim.x + threadIdx.x;
    if (idx >= SS * 64) return;
    int t = idx >> 6;
    int j = idx & 63;
    double theta = (double)t * pow(10000.0, -(double)j / 64.0);
    g_cos[idx] = (float)cos(theta);
    g_sin[idx] = (float)sin(theta);
}

// ---------------- classic 128x128x8 SGEMM, C = A@B + bias ----------------
// A: [M,K] row-major, B: [K,N] row-major, bias: [N]
__global__ void __launch_bounds__(256) sgemm_kernel(
    const float* __restrict__ A, const float* __restrict__ Bm,
    const float* __restrict__ bias, float* __restrict__ C,
    int M, int N, int K)
{
    const int BM = 128, BN = 128, BK = 8;
    __shared__ float As[BK][BM];   // transposed A tile
    __shared__ float Bs[BK][BN];

    int tid = threadIdx.x;
    int tr = tid >> 4;          // 0..15
    int tc = tid & 15;          // 0..15
    int rowBase = blockIdx.y * BM;
    int colBase = blockIdx.x * BN;

    float acc[8][8];
#pragma unroll
    for (int i = 0; i < 8; i++)
#pragma unroll
        for (int j = 0; j < 8; j++) acc[i][j] = 0.f;

    int aRow = tid >> 1;            // 0..127
    int aCol = (tid & 1) * 4;       // 0 or 4
    int bRow = tid >> 5;            // 0..7
    int bCol = (tid & 31) * 4;      // 0..124

    const float* Aptr = A + (size_t)(rowBase + aRow) * K + aCol;
    const float* Bptr = Bm + (size_t)bRow * N + colBase + bCol;

    for (int k0 = 0; k0 < K; k0 += BK) {
        float4 a4 = *(const float4*)(Aptr + k0);
        As[aCol + 0][aRow] = a4.x;
        As[aCol + 1][aRow] = a4.y;
        As[aCol + 2][aRow] = a4.z;
        As[aCol + 3][aRow] = a4.w;
        float4 b4 = *(const float4*)(Bptr + (size_t)k0 * N);
        *(float4*)&Bs[bRow][bCol] = b4;
        __syncthreads();

#pragma unroll
        for (int kk = 0; kk < BK; kk++) {
            float ar[8], br[8];
            float4 t0 = *(const float4*)&As[kk][tr * 8];
            float4 t1 = *(const float4*)&As[kk][tr * 8 + 4];
            ar[0]=t0.x; ar[1]=t0.y; ar[2]=t0.z; ar[3]=t0.w;
            ar[4]=t1.x; ar[5]=t1.y; ar[6]=t1.z; ar[7]=t1.w;
            float4 u0 = *(const float4*)&Bs[kk][tc * 8];
            float4 u1 = *(const float4*)&Bs[kk][tc * 8 + 4];
            br[0]=u0.x; br[1]=u0.y; br[2]=u0.z; br[3]=u0.w;
            br[4]=u1.x; br[5]=u1.y; br[6]=u1.z; br[7]=u1.w;
#pragma unroll
            for (int i = 0; i < 8; i++)
#pragma unroll
                for (int j = 0; j < 8; j++)
                    acc[i][j] += ar[i] * br[j];
        }
        __syncthreads();
    }

#pragma unroll
    for (int i = 0; i < 8; i++) {
        int r = rowBase + tr * 8 + i;
        float* Crow = C + (size_t)r * N + colBase + tc * 8;
        const float* brow = bias + colBase + tc * 8;
#pragma unroll
        for (int j = 0; j < 8; j++)
            Crow[j] = acc[i][j] + brow[j];
    }
}

// ---------------- RoPE + split + transpose to [B,H,S,DH] ----------------
// rotate(u)[i] = u[2i+1] for i<64 ; rotate(u)[64+i] = -u[2i]
// out[i]    = u[i]   *cos_j + u[2j+1]*sin_j   (j = i)
// out[j+64] = u[j+64]*cos_j - u[2j]  *sin_j
__global__ void rope_split_kernel() {
    int idx = blockIdx.x * blockDim.x + threadIdx.x;
    if (idx >= BB * HH * SS * 64) return;
    int j = idx & 63;
    int s = (idx >> 6) & (SS - 1);
    int h = (idx >> 17) & (HH - 1);   // 64*2048 = 2^17
    int b = idx >> 21;                // 64*2048*16 = 2^21

    const float* qrow = g_qkv + (size_t)(b * SS + s) * ND3 + h * DHH;
    const float* krow = qrow + DD;
    const float* vrow = qrow + 2 * DD;
    float c  = g_cos[s * 64 + j];
    float sn = g_sin[s * 64 + j];
    size_t o = ((size_t)(b * HH + h) * SS + s) * DHH;

    const float qscale = 0.088388347648318447f;  // 1/sqrt(128), folded into Q

    float u0 = qrow[j], u1 = qrow[j + 64], ue = qrow[2 * j], uo = qrow[2 * j + 1];
    g_q[o + j]      = (u0 * c + uo * sn) * qscale;
    g_q[o + j + 64] = (u1 * c - ue * sn) * qscale;

    u0 = krow[j]; u1 = krow[j + 64]; ue = krow[2 * j]; uo = krow[2 * j + 1];
    g_k[o + j]      = u0 * c + uo * sn;
    g_k[o + j + 64] = u1 * c - ue * sn;

    g_v[o + j]      = vrow[j];
    g_v[o + j + 64] = vrow[j + 64];
}

// ---------------- streaming-softmax attention ----------------
// grid: (S/64, B*H). 256 threads. BM=64 queries, BN=64 keys per step, DH=128.
// Q/K smem padded to 129 floats/row (conflict-free column reads).
#define ATTN_SMEM_FLOATS (64*129 + 64*129 + 64*128 + 64*65 + 64 + 64)
#define ATTN_SMEM_BYTES  (ATTN_SMEM_FLOATS * 4)

__global__ void __launch_bounds__(256) attn_kernel() {
    extern __shared__ float sm[];
    float* Qs = sm;                      // [64][129]
    float* Ks = Qs + 64 * 129;           // [64][129]
    float* Vs = Ks + 64 * 129;           // [64][128]
    float* Ps = Vs + 64 * 128;           // [64][65]
    float* rowScale = Ps + 64 * 65;      // [64]
    float* rowL     = rowScale + 64;     // [64]

    int tid = threadIdx.x;
    int tr = tid >> 4;   // 0..15 -> rows {tr, tr+16, tr+32, tr+48}
    int tc = tid & 15;   // 0..15 -> score cols {tc+16j}, O cols {tc+16j, j<8}

    int bh = blockIdx.y;
    int b = bh >> 4, h = bh & 15;
    int q0 = blockIdx.x * 64;

    const float* Qg = g_q + (size_t)bh * SS * DHH;
    const float* Kg = g_k + (size_t)bh * SS * DHH;
    const float* Vg = g_v + (size_t)bh * SS * DHH;

    // load Q tile (already scaled by 1/sqrt(DH))
    for (int c = tid; c < 64 * 32; c += 256) {
        int r = c >> 5;
        int d4 = (c & 31) * 4;
        float4 q4 = *(const float4*)(Qg + (size_t)(q0 + r) * DHH + d4);
        Qs[r * 129 + d4 + 0] = q4.x;
        Qs[r * 129 + d4 + 1] = q4.y;
        Qs[r * 129 + d4 + 2] = q4.z;
        Qs[r * 129 + d4 + 3] = q4.w;
    }

    float o[4][8];
#pragma unroll
    for (int i = 0; i < 4; i++)
#pragma unroll
        for (int j = 0; j < 8; j++) o[i][j] = 0.f;

    float m_r = -1e30f, l_r = 0.f;   // live only in tid<64

    for (int kt = 0; kt < SS / 64; kt++) {
        // load K,V tiles
        for (int c = tid; c < 64 * 32; c += 256) {
            int r = c >> 5;
            int d4 = (c & 31) * 4;
            float4 k4 = *(const float4*)(Kg + (size_t)(kt * 64 + r) * DHH + d4);
            Ks[r * 129 + d4 + 0] = k4.x;
            Ks[r * 129 + d4 + 1] = k4.y;
            Ks[r * 129 + d4 + 2] = k4.z;
            Ks[r * 129 + d4 + 3] = k4.w;
            float4 v4 = *(const float4*)(Vg + (size_t)(kt * 64 + r) * DHH + d4);
            *(float4*)&Vs[r * 128 + d4] = v4;
        }
        __syncthreads();

        // S = Q K^T  (4x4 per thread, strided rows/cols)
        float sacc[4][4];
#pragma unroll
        for (int i = 0; i < 4; i++)
#pragma unroll
            for (int j = 0; j < 4; j++) sacc[i][j] = 0.f;

#pragma unroll 4
        for (int d = 0; d < DHH; d++) {
            float a0 = Qs[(tr     ) * 129 + d];
            float a1 = Qs[(tr + 16) * 129 + d];
            float a2 = Qs[(tr + 32) * 129 + d];
            float a3 = Qs[(tr + 48) * 129 + d];
            float b0 = Ks[(tc     ) * 129 + d];
            float b1 = Ks[(tc + 16) * 129 + d];
            float b2 = Ks[(tc + 32) * 129 + d];
            float b3 = Ks[(tc + 48) * 129 + d];
            sacc[0][0] += a0*b0; sacc[0][1] += a0*b1; sacc[0][2] += a0*b2; sacc[0][3] += a0*b3;
            sacc[1][0] += a1*b0; sacc[1][1] += a1*b1; sacc[1][2] += a1*b2; sacc[1][3] += a1*b3;
            sacc[2][0] += a2*b0; sacc[2][1] += a2*b1; sacc[2][2] += a2*b2; sacc[2][3] += a2*b3;
            sacc[3][0] += a3*b0; sacc[3][1] += a3*b1; sacc[3][2] += a3*b2; sacc[3][3] += a3*b3;
        }
#pragma unroll
        for (int i = 0; i < 4; i++)
#pragma unroll
            for (int j = 0; j < 4; j++)
                Ps[(tr + 16 * i) * 65 + tc + 16 * j] = sacc[i][j];
        __syncthreads();

        // online softmax per row (threads 0..63)
        if (tid < 64) {
            float mx = -1e30f;
            for (int k2 = 0; k2 < 64; k2++) mx = fmaxf(mx, Ps[tid * 65 + k2]);
            float newm = fmaxf(m_r, mx);
            float scale = __expf(m_r - newm);
            float ps = 0.f;
            for (int k2 = 0; k2 < 64; k2++) {
                float p = __expf(Ps[tid * 65 + k2] - newm);
                Ps[tid * 65 + k2] = p;
                ps += p;
            }
            l_r = l_r * scale + ps;
            m_r = newm;
            rowScale[tid] = scale;
        }
        __syncthreads();

        // rescale O, accumulate P @ V
        float f0 = rowScale[tr], f1 = rowScale[tr + 16];
        float f2 = rowScale[tr + 32], f3 = rowScale[tr + 48];
#pragma unroll
        for (int j = 0; j < 8; j++) {
            o[0][j] *= f0; o[1][j] *= f1; o[2][j] *= f2; o[3][j] *= f3;
        }
#pragma unroll 2
        for (int kk = 0; kk < 64; kk++) {
            float p0 = Ps[(tr     ) * 65 + kk];
            float p1 = Ps[(tr + 16) * 65 + kk];
            float p2 = Ps[(tr + 32) * 65 + kk];
            float p3 = Ps[(tr + 48) * 65 + kk];
#pragma unroll
            for (int j = 0; j < 8; j++) {
                float v = Vs[kk * 128 + tc + 16 * j];
                o[0][j] += p0 * v;
                o[1][j] += p1 * v;
                o[2][j] += p2 * v;
                o[3][j] += p3 * v;
            }
        }
        __syncthreads();
    }

    if (tid < 64) rowL[tid] = l_r;
    __syncthreads();

    float inv0 = 1.f / rowL[tr],      inv1 = 1.f / rowL[tr + 16];
    float inv2 = 1.f / rowL[tr + 32], inv3 = 1.f / rowL[tr + 48];
    float invs[4] = {inv0, inv1, inv2, inv3};
#pragma unroll
    for (int i = 0; i < 4; i++) {
        int r = q0 + tr + 16 * i;
        float* dst = g_ctx + (size_t)(b * SS + r) * DD + h * DHH;
#pragma unroll
        for (int j = 0; j < 8; j++)
            dst[tc + 16 * j] = o[i][j] * invs[i];
    }
}

// ---------------- launch ----------------
extern "C" void kernel_launch(void* const* d_in, const int* in_sizes, int n_in,
                              void* d_out, int out_size) {
    const float* x    = (const float*)d_in[0];
    const float* Wqkv = (const float*)d_in[1];
    const float* bqkv = (const float*)d_in[2];
    const float* Wo   = (const float*)d_in[3];
    const float* bo   = (const float*)d_in[4];
    float* out = (float*)d_out;

    void *qkvPtr, *ctxPtr;
    cudaGetSymbolAddress(&qkvPtr, g_qkv);
    cudaGetSymbolAddress(&ctxPtr, g_ctx);

    cudaFuncSetAttribute(attn_kernel,
                         cudaFuncAttributeMaxDynamicSharedMemorySize,
                         ATTN_SMEM_BYTES);

    // 1) RoPE tables
    rope_table_kernel<<<(SS * 64 + 255) / 256, 256>>>();

    // 2) QKV GEMM: [4096,2048] @ [2048,6144] + bqkv
    sgemm_kernel<<<dim3(ND3 / 128, (BB * SS) / 128), 256>>>(
        x, Wqkv, bqkv, (float*)qkvPtr, BB * SS, ND3, DD);

    // 3) RoPE + split/transpose (+ fold 1/sqrt(DH) into Q)
    rope_split_kernel<<<(BB * HH * SS * 64) / 256, 256>>>();

    // 4) attention -> g_ctx in [B,S,H*DH]
    attn_kernel<<<dim3(SS / 64, BB * HH), 256, ATTN_SMEM_BYTES>>>();

    // 5) output projection: [4096,2048] @ [2048,2048] + bo -> d_out
    sgemm_kernel<<<dim3(DD / 128, (BB * SS) / 128), 256>>>(
        (const float*)ctxPtr, Wo, bo, out, BB * SS, DD, DD);
}

// round 4
// speedup vs baseline: 1.5102x; 1.5102x over previous
#include <cuda_runtime.h>
#include <math.h>
#include <stdint.h>

#define BB 2
#define SS 2048
#define DD 2048
#define HH 16
#define DHH 128
#define ND3 (3*DD)

// ---------------- scratch (static device globals; no allocation) ----------------
__device__ float g_qkv[(size_t)BB*SS*ND3];      // [B,S,3D]
__device__ float g_q  [(size_t)BB*HH*SS*DHH];   // [B,H,S,DH] (pre-scaled by 1/sqrt(DH))
__device__ float g_k  [(size_t)BB*HH*SS*DHH];
__device__ float g_v  [(size_t)BB*HH*SS*DHH];
__device__ float g_ctx[(size_t)BB*SS*DD];       // [B,S,H*DH]
__device__ float g_cos[SS*64];
__device__ float g_sin[SS*64];

__device__ __forceinline__ uint32_t f32_to_tf32(float x) {
    uint32_t r;
    asm("cvt.rna.tf32.f32 %0, %1;" : "=r"(r) : "f"(x));
    return r;
}

// ==================== tf32 mma.sync GEMM: C[M,N] = A[M,K] @ B[K,N] + bias ====================
// 128x128 CTA tile, 256 threads = 8 warps, each warp 64x32 (4x4 m16n8k8 tiles).
// K-chunk 32, register-prefetch of next chunk overlapped with mma compute.
#define GBM 128
#define GBN 128
#define GBK 32
#define A_STR 36    // padded row stride (floats) for A tile [128][32]
#define B_STR 132   // padded row stride (floats) for B tile [32][128]

__global__ void __launch_bounds__(256) mma_gemm_kernel(
    const float* __restrict__ A, const float* __restrict__ Bm,
    const float* __restrict__ bias, float* __restrict__ C,
    int M, int N, int K)
{
    __shared__ uint32_t As[GBM * A_STR];
    __shared__ uint32_t Bs[GBK * B_STR];

    int tid  = threadIdx.x;
    int lane = tid & 31;
    int w    = tid >> 5;
    int wr   = w >> 2;      // 0..1 (64-row block)
    int wc   = w & 3;       // 0..3 (32-col block)
    int grp  = lane >> 2;   // 0..7
    int tig  = lane & 3;    // 0..3
    int m0 = blockIdx.y * GBM;
    int n0 = blockIdx.x * GBN;

    float acc[4][4][4];
#pragma unroll
    for (int mt = 0; mt < 4; mt++)
#pragma unroll
        for (int nt = 0; nt < 4; nt++)
#pragma unroll
            for (int i = 0; i < 4; i++) acc[mt][nt][i] = 0.f;

    float4 pa[4], pb[4];
#pragma unroll
    for (int i = 0; i < 4; i++) {
        int s = tid + i * 256;
        int ar = s >> 3, ac = (s & 7) * 4;
        pa[i] = *(const float4*)(A + (size_t)(m0 + ar) * K + ac);
        int br = s >> 5, bc = (s & 31) * 4;
        pb[i] = *(const float4*)(Bm + (size_t)br * N + n0 + bc);
    }

    const int nCh = K / GBK;
    for (int kc = 0; kc < nCh; kc++) {
#pragma unroll
        for (int i = 0; i < 4; i++) {
            int s = tid + i * 256;
            int ar = s >> 3, ac = (s & 7) * 4;
            uint4 t;
            t.x = f32_to_tf32(pa[i].x); t.y = f32_to_tf32(pa[i].y);
            t.z = f32_to_tf32(pa[i].z); t.w = f32_to_tf32(pa[i].w);
            *(uint4*)&As[ar * A_STR + ac] = t;
            int br = s >> 5, bc = (s & 31) * 4;
            t.x = f32_to_tf32(pb[i].x); t.y = f32_to_tf32(pb[i].y);
            t.z = f32_to_tf32(pb[i].z); t.w = f32_to_tf32(pb[i].w);
            *(uint4*)&Bs[br * B_STR + bc] = t;
        }
        __syncthreads();

        if (kc + 1 < nCh) {
            int k0 = (kc + 1) * GBK;
#pragma unroll
            for (int i = 0; i < 4; i++) {
                int s = tid + i * 256;
                int ar = s >> 3, ac = (s & 7) * 4;
                pa[i] = *(const float4*)(A + (size_t)(m0 + ar) * K + k0 + ac);
                int br = s >> 5, bc = (s & 31) * 4;
                pb[i] = *(const float4*)(Bm + (size_t)(k0 + br) * N + n0 + bc);
            }
        }

#pragma unroll
        for (int kk = 0; kk < 4; kk++) {
            uint32_t af[4][4], bf[4][2];
#pragma unroll
            for (int mt = 0; mt < 4; mt++) {
                int r = wr * 64 + mt * 16 + grp;
                int kb = kk * 8 + tig;
                af[mt][0] = As[r * A_STR + kb];
                af[mt][1] = As[(r + 8) * A_STR + kb];
                af[mt][2] = As[r * A_STR + kb + 4];
                af[mt][3] = As[(r + 8) * A_STR + kb + 4];
            }
#pragma unroll
            for (int nt = 0; nt < 4; nt++) {
                int cn = wc * 32 + nt * 8 + grp;
                bf[nt][0] = Bs[(kk * 8 + tig) * B_STR + cn];
                bf[nt][1] = Bs[(kk * 8 + tig + 4) * B_STR + cn];
            }
#pragma unroll
            for (int mt = 0; mt < 4; mt++)
#pragma unroll
                for (int nt = 0; nt < 4; nt++) {
                    asm volatile(
                        "mma.sync.aligned.m16n8k8.row.col.f32.tf32.tf32.f32 "
                        "{%0,%1,%2,%3}, {%4,%5,%6,%7}, {%8,%9}, {%0,%1,%2,%3};"
                        : "+f"(acc[mt][nt][0]), "+f"(acc[mt][nt][1]),
                          "+f"(acc[mt][nt][2]), "+f"(acc[mt][nt][3])
                        : "r"(af[mt][0]), "r"(af[mt][1]), "r"(af[mt][2]), "r"(af[mt][3]),
                          "r"(bf[nt][0]), "r"(bf[nt][1]));
                }
        }
        __syncthreads();
    }

    // epilogue: c0,c1 -> row grp, cols 2*tig, 2*tig+1 ; c2,c3 -> row grp+8
#pragma unroll
    for (int mt = 0; mt < 4; mt++) {
        int r0 = m0 + wr * 64 + mt * 16 + grp;
#pragma unroll
        for (int nt = 0; nt < 4; nt++) {
            int cn = n0 + wc * 32 + nt * 8 + tig * 2;
            float b0 = bias[cn], b1 = bias[cn + 1];
            float2 v0 = make_float2(acc[mt][nt][0] + b0, acc[mt][nt][1] + b1);
            float2 v1 = make_float2(acc[mt][nt][2] + b0, acc[mt][nt][3] + b1);
            *(float2*)(C + (size_t)r0 * N + cn) = v0;
            *(float2*)(C + (size_t)(r0 + 8) * N + cn) = v1;
        }
    }
}

// ---------------- RoPE tables (double trig for accuracy) ----------------
__global__ void rope_table_kernel() {
    int idx = blockIdx.x * blockDim.x + threadIdx.x;
    if (idx >= SS * 64) return;
    int t = idx >> 6;
    int j = idx & 63;
    double theta = (double)t * pow(10000.0, -(double)j / 64.0);
    g_cos[idx] = (float)cos(theta);
    g_sin[idx] = (float)sin(theta);
}

// ---------------- RoPE + split + transpose to [B,H,S,DH] ----------------
__global__ void rope_split_kernel() {
    int idx = blockIdx.x * blockDim.x + threadIdx.x;
    if (idx >= BB * HH * SS * 64) return;
    int j = idx & 63;
    int s = (idx >> 6) & (SS - 1);
    int h = (idx >> 17) & (HH - 1);
    int b = idx >> 21;

    const float* qrow = g_qkv + (size_t)(b * SS + s) * ND3 + h * DHH;
    const float* krow = qrow + DD;
    const float* vrow = qrow + 2 * DD;
    float c  = g_cos[s * 64 + j];
    float sn = g_sin[s * 64 + j];
    size_t o = ((size_t)(b * HH + h) * SS + s) * DHH;

    const float qscale = 0.088388347648318447f;  // 1/sqrt(128)

    float u0 = qrow[j], u1 = qrow[j + 64], ue = qrow[2 * j], uo = qrow[2 * j + 1];
    g_q[o + j]      = (u0 * c + uo * sn) * qscale;
    g_q[o + j + 64] = (u1 * c - ue * sn) * qscale;

    u0 = krow[j]; u1 = krow[j + 64]; ue = krow[2 * j]; uo = krow[2 * j + 1];
    g_k[o + j]      = u0 * c + uo * sn;
    g_k[o + j + 64] = u1 * c - ue * sn;

    g_v[o + j]      = vrow[j];
    g_v[o + j + 64] = vrow[j + 64];
}

// ---------------- streaming-softmax attention (fp32 FMA) ----------------
#define ATTN_SMEM_FLOATS (64*129 + 64*129 + 64*128 + 64*65 + 64 + 64)
#define ATTN_SMEM_BYTES  (ATTN_SMEM_FLOATS * 4)

__global__ void __launch_bounds__(256) attn_kernel() {
    extern __shared__ float sm[];
    float* Qs = sm;
    float* Ks = Qs + 64 * 129;
    float* Vs = Ks + 64 * 129;
    float* Ps = Vs + 64 * 128;
    float* rowScale = Ps + 64 * 65;
    float* rowL     = rowScale + 64;

    int tid = threadIdx.x;
    int tr = tid >> 4;
    int tc = tid & 15;

    int bh = blockIdx.y;
    int b = bh >> 4, h = bh & 15;
    int q0 = blockIdx.x * 64;

    const float* Qg = g_q + (size_t)bh * SS * DHH;
    const float* Kg = g_k + (size_t)bh * SS * DHH;
    const float* Vg = g_v + (size_t)bh * SS * DHH;

    for (int c = tid; c < 64 * 32; c += 256) {
        int r = c >> 5;
        int d4 = (c & 31) * 4;
        float4 q4 = *(const float4*)(Qg + (size_t)(q0 + r) * DHH + d4);
        Qs[r * 129 + d4 + 0] = q4.x;
        Qs[r * 129 + d4 + 1] = q4.y;
        Qs[r * 129 + d4 + 2] = q4.z;
        Qs[r * 129 + d4 + 3] = q4.w;
    }

    float o[4][8];
#pragma unroll
    for (int i = 0; i < 4; i++)
#pragma unroll
        for (int j = 0; j < 8; j++) o[i][j] = 0.f;

    float m_r = -1e30f, l_r = 0.f;

    for (int kt = 0; kt < SS / 64; kt++) {
        for (int c = tid; c < 64 * 32; c += 256) {
            int r = c >> 5;
            int d4 = (c & 31) * 4;
            float4 k4 = *(const float4*)(Kg + (size_t)(kt * 64 + r) * DHH + d4);
            Ks[r * 129 + d4 + 0] = k4.x;
            Ks[r * 129 + d4 + 1] = k4.y;
            Ks[r * 129 + d4 + 2] = k4.z;
            Ks[r * 129 + d4 + 3] = k4.w;
            float4 v4 = *(const float4*)(Vg + (size_t)(kt * 64 + r) * DHH + d4);
            *(float4*)&Vs[r * 128 + d4] = v4;
        }
        __syncthreads();

        float sacc[4][4];
#pragma unroll
        for (int i = 0; i < 4; i++)
#pragma unroll
            for (int j = 0; j < 4; j++) sacc[i][j] = 0.f;

#pragma unroll 4
        for (int d = 0; d < DHH; d++) {
            float a0 = Qs[(tr     ) * 129 + d];
            float a1 = Qs[(tr + 16) * 129 + d];
            float a2 = Qs[(tr + 32) * 129 + d];
            float a3 = Qs[(tr + 48) * 129 + d];
            float b0 = Ks[(tc     ) * 129 + d];
            float b1 = Ks[(tc + 16) * 129 + d];
            float b2 = Ks[(tc + 32) * 129 + d];
            float b3 = Ks[(tc + 48) * 129 + d];
            sacc[0][0] += a0*b0; sacc[0][1] += a0*b1; sacc[0][2] += a0*b2; sacc[0][3] += a0*b3;
            sacc[1][0] += a1*b0; sacc[1][1] += a1*b1; sacc[1][2] += a1*b2; sacc[1][3] += a1*b3;
            sacc[2][0] += a2*b0; sacc[2][1] += a2*b1; sacc[2][2] += a2*b2; sacc[2][3] += a2*b3;
            sacc[3][0] += a3*b0; sacc[3][1] += a3*b1; sacc[3][2] += a3*b2; sacc[3][3] += a3*b3;
        }
#pragma unroll
        for (int i = 0; i < 4; i++)
#pragma unroll
            for (int j = 0; j < 4; j++)
                Ps[(tr + 16 * i) * 65 + tc + 16 * j] = sacc[i][j];
        __syncthreads();

        if (tid < 64) {
            float mx = -1e30f;
            for (int k2 = 0; k2 < 64; k2++) mx = fmaxf(mx, Ps[tid * 65 + k2]);
            float newm = fmaxf(m_r, mx);
            float scale = __expf(m_r - newm);
            float ps = 0.f;
            for (int k2 = 0; k2 < 64; k2++) {
                float p = __expf(Ps[tid * 65 + k2] - newm);
                Ps[tid * 65 + k2] = p;
                ps += p;
            }
            l_r = l_r * scale + ps;
            m_r = newm;
            rowScale[tid] = scale;
        }
        __syncthreads();

        float f0 = rowScale[tr], f1 = rowScale[tr + 16];
        float f2 = rowScale[tr + 32], f3 = rowScale[tr + 48];
#pragma unroll
        for (int j = 0; j < 8; j++) {
            o[0][j] *= f0; o[1][j] *= f1; o[2][j] *= f2; o[3][j] *= f3;
        }
#pragma unroll 2
        for (int kk = 0; kk < 64; kk++) {
            float p0 = Ps[(tr     ) * 65 + kk];
            float p1 = Ps[(tr + 16) * 65 + kk];
            float p2 = Ps[(tr + 32) * 65 + kk];
            float p3 = Ps[(tr + 48) * 65 + kk];
#pragma unroll
            for (int j = 0; j < 8; j++) {
                float v = Vs[kk * 128 + tc + 16 * j];
                o[0][j] += p0 * v;
                o[1][j] += p1 * v;
                o[2][j] += p2 * v;
                o[3][j] += p3 * v;
            }
        }
        __syncthreads();
    }

    if (tid < 64) rowL[tid] = l_r;
    __syncthreads();

    float inv0 = 1.f / rowL[tr],      inv1 = 1.f / rowL[tr + 16];
    float inv2 = 1.f / rowL[tr + 32], inv3 = 1.f / rowL[tr + 48];
    float invs[4] = {inv0, inv1, inv2, inv3};
#pragma unroll
    for (int i = 0; i < 4; i++) {
        int r = q0 + tr + 16 * i;
        float* dst = g_ctx + (size_t)(b * SS + r) * DD + h * DHH;
#pragma unroll
        for (int j = 0; j < 8; j++)
            dst[tc + 16 * j] = o[i][j] * invs[i];
    }
}

// ---------------- launch ----------------
extern "C" void kernel_launch(void* const* d_in, const int* in_sizes, int n_in,
                              void* d_out, int out_size) {
    const float* x    = (const float*)d_in[0];
    const float* Wqkv = (const float*)d_in[1];
    const float* bqkv = (const float*)d_in[2];
    const float* Wo   = (const float*)d_in[3];
    const float* bo   = (const float*)d_in[4];
    float* out = (float*)d_out;

    void *qkvPtr, *ctxPtr;
    cudaGetSymbolAddress(&qkvPtr, g_qkv);
    cudaGetSymbolAddress(&ctxPtr, g_ctx);

    cudaFuncSetAttribute(attn_kernel,
                         cudaFuncAttributeMaxDynamicSharedMemorySize,
                         ATTN_SMEM_BYTES);

    // 1) RoPE tables
    rope_table_kernel<<<(SS * 64 + 255) / 256, 256>>>();

    // 2) QKV GEMM (tf32 mma.sync): [4096,2048] @ [2048,6144] + bqkv
    mma_gemm_kernel<<<dim3(ND3 / 128, (BB * SS) / 128), 256>>>(
        x, Wqkv, bqkv, (float*)qkvPtr, BB * SS, ND3, DD);

    // 3) RoPE + split/transpose (+ fold 1/sqrt(DH) into Q)
    rope_split_kernel<<<(BB * HH * SS * 64) / 256, 256>>>();

    // 4) attention -> g_ctx in [B,S,H*DH]
    attn_kernel<<<dim3(SS / 64, BB * HH), 256, ATTN_SMEM_BYTES>>>();

    // 5) output projection (tf32 mma.sync): [4096,2048] @ [2048,2048] + bo
    mma_gemm_kernel<<<dim3(DD / 128, (BB * SS) / 128), 256>>>(
        (const float*)ctxPtr, Wo, bo, out, BB * SS, DD, DD);
}

// round 5
// speedup vs baseline: 3.0729x; 2.0348x over previous
#include <cuda_runtime.h>
#include <math.h>
#include <stdint.h>

#define BB 2
#define SS 2048
#define DD 2048
#define HH 16
#define DHH 128
#define ND3 (3*DD)

// ---------------- scratch (static device globals; no allocation) ----------------
__device__ float g_qkv[(size_t)BB*SS*ND3];      // [B,S,3D]
__device__ float g_q  [(size_t)BB*HH*SS*DHH];   // [B,H,S,DH] (pre-scaled by 1/sqrt(DH))
__device__ float g_k  [(size_t)BB*HH*SS*DHH];
__device__ float g_v  [(size_t)BB*HH*SS*DHH];
__device__ float g_ctx[(size_t)BB*SS*DD];       // [B,S,H*DH]
__device__ float g_cos[SS*64];
__device__ float g_sin[SS*64];

__device__ __forceinline__ uint32_t f32_to_tf32(float x) {
    uint32_t r;
    asm("cvt.rna.tf32.f32 %0, %1;" : "=r"(r) : "f"(x));
    return r;
}

#define MMA_TF32(c0,c1,c2,c3,a0,a1,a2,a3,b0,b1)                          \
    asm volatile(                                                        \
        "mma.sync.aligned.m16n8k8.row.col.f32.tf32.tf32.f32 "            \
        "{%0,%1,%2,%3}, {%4,%5,%6,%7}, {%8,%9}, {%0,%1,%2,%3};"          \
        : "+f"(c0), "+f"(c1), "+f"(c2), "+f"(c3)                         \
        : "r"(a0), "r"(a1), "r"(a2), "r"(a3), "r"(b0), "r"(b1))

// ==================== tf32 mma.sync GEMM: C[M,N] = A[M,K] @ B[K,N] + bias ====================
#define GBM 128
#define GBN 128
#define GBK 32
#define A_STR 36
#define B_STR 132

__global__ void __launch_bounds__(256) mma_gemm_kernel(
    const float* __restrict__ A, const float* __restrict__ Bm,
    const float* __restrict__ bias, float* __restrict__ C,
    int M, int N, int K)
{
    __shared__ uint32_t As[GBM * A_STR];
    __shared__ uint32_t Bs[GBK * B_STR];

    int tid  = threadIdx.x;
    int lane = tid & 31;
    int w    = tid >> 5;
    int wr   = w >> 2;
    int wc   = w & 3;
    int grp  = lane >> 2;
    int tig  = lane & 3;
    int m0 = blockIdx.y * GBM;
    int n0 = blockIdx.x * GBN;

    float acc[4][4][4];
#pragma unroll
    for (int mt = 0; mt < 4; mt++)
#pragma unroll
        for (int nt = 0; nt < 4; nt++)
#pragma unroll
            for (int i = 0; i < 4; i++) acc[mt][nt][i] = 0.f;

    float4 pa[4], pb[4];
#pragma unroll
    for (int i = 0; i < 4; i++) {
        int s = tid + i * 256;
        int ar = s >> 3, ac = (s & 7) * 4;
        pa[i] = *(const float4*)(A + (size_t)(m0 + ar) * K + ac);
        int br = s >> 5, bc = (s & 31) * 4;
        pb[i] = *(const float4*)(Bm + (size_t)br * N + n0 + bc);
    }

    const int nCh = K / GBK;
    for (int kc = 0; kc < nCh; kc++) {
#pragma unroll
        for (int i = 0; i < 4; i++) {
            int s = tid + i * 256;
            int ar = s >> 3, ac = (s & 7) * 4;
            uint4 t;
            t.x = f32_to_tf32(pa[i].x); t.y = f32_to_tf32(pa[i].y);
            t.z = f32_to_tf32(pa[i].z); t.w = f32_to_tf32(pa[i].w);
            *(uint4*)&As[ar * A_STR + ac] = t;
            int br = s >> 5, bc = (s & 31) * 4;
            t.x = f32_to_tf32(pb[i].x); t.y = f32_to_tf32(pb[i].y);
            t.z = f32_to_tf32(pb[i].z); t.w = f32_to_tf32(pb[i].w);
            *(uint4*)&Bs[br * B_STR + bc] = t;
        }
        __syncthreads();

        if (kc + 1 < nCh) {
            int k0 = (kc + 1) * GBK;
#pragma unroll
            for (int i = 0; i < 4; i++) {
                int s = tid + i * 256;
                int ar = s >> 3, ac = (s & 7) * 4;
                pa[i] = *(const float4*)(A + (size_t)(m0 + ar) * K + k0 + ac);
                int br = s >> 5, bc = (s & 31) * 4;
                pb[i] = *(const float4*)(Bm + (size_t)(k0 + br) * N + n0 + bc);
            }
        }

#pragma unroll
        for (int kk = 0; kk < 4; kk++) {
            uint32_t af[4][4], bf[4][2];
#pragma unroll
            for (int mt = 0; mt < 4; mt++) {
                int r = wr * 64 + mt * 16 + grp;
                int kb = kk * 8 + tig;
                af[mt][0] = As[r * A_STR + kb];
                af[mt][1] = As[(r + 8) * A_STR + kb];
                af[mt][2] = As[r * A_STR + kb + 4];
                af[mt][3] = As[(r + 8) * A_STR + kb + 4];
            }
#pragma unroll
            for (int nt = 0; nt < 4; nt++) {
                int cn = wc * 32 + nt * 8 + grp;
                bf[nt][0] = Bs[(kk * 8 + tig) * B_STR + cn];
                bf[nt][1] = Bs[(kk * 8 + tig + 4) * B_STR + cn];
            }
#pragma unroll
            for (int mt = 0; mt < 4; mt++)
#pragma unroll
                for (int nt = 0; nt < 4; nt++)
                    MMA_TF32(acc[mt][nt][0], acc[mt][nt][1], acc[mt][nt][2], acc[mt][nt][3],
                             af[mt][0], af[mt][1], af[mt][2], af[mt][3],
                             bf[nt][0], bf[nt][1]);
        }
        __syncthreads();
    }

#pragma unroll
    for (int mt = 0; mt < 4; mt++) {
        int r0 = m0 + wr * 64 + mt * 16 + grp;
#pragma unroll
        for (int nt = 0; nt < 4; nt++) {
            int cn = n0 + wc * 32 + nt * 8 + tig * 2;
            float b0 = bias[cn], b1 = bias[cn + 1];
            float2 v0 = make_float2(acc[mt][nt][0] + b0, acc[mt][nt][1] + b1);
            float2 v1 = make_float2(acc[mt][nt][2] + b0, acc[mt][nt][3] + b1);
            *(float2*)(C + (size_t)r0 * N + cn) = v0;
            *(float2*)(C + (size_t)(r0 + 8) * N + cn) = v1;
        }
    }
}

// ---------------- RoPE tables ----------------
__global__ void rope_table_kernel() {
    int idx = blockIdx.x * blockDim.x + threadIdx.x;
    if (idx >= SS * 64) return;
    int t = idx >> 6;
    int j = idx & 63;
    double theta = (double)t * pow(10000.0, -(double)j / 64.0);
    g_cos[idx] = (float)cos(theta);
    g_sin[idx] = (float)sin(theta);
}

// ---------------- RoPE + split + transpose to [B,H,S,DH] ----------------
__global__ void rope_split_kernel() {
    int idx = blockIdx.x * blockDim.x + threadIdx.x;
    if (idx >= BB * HH * SS * 64) return;
    int j = idx & 63;
    int s = (idx >> 6) & (SS - 1);
    int h = (idx >> 17) & (HH - 1);
    int b = idx >> 21;

    const float* qrow = g_qkv + (size_t)(b * SS + s) * ND3 + h * DHH;
    const float* krow = qrow + DD;
    const float* vrow = qrow + 2 * DD;
    float c  = g_cos[s * 64 + j];
    float sn = g_sin[s * 64 + j];
    size_t o = ((size_t)(b * HH + h) * SS + s) * DHH;

    const float qscale = 0.088388347648318447f;  // 1/sqrt(128)

    float u0 = qrow[j], u1 = qrow[j + 64], ue = qrow[2 * j], uo = qrow[2 * j + 1];
    g_q[o + j]      = (u0 * c + uo * sn) * qscale;
    g_q[o + j + 64] = (u1 * c - ue * sn) * qscale;

    u0 = krow[j]; u1 = krow[j + 64]; ue = krow[2 * j]; uo = krow[2 * j + 1];
    g_k[o + j]      = u0 * c + uo * sn;
    g_k[o + j + 64] = u1 * c - ue * sn;

    g_v[o + j]      = vrow[j];
    g_v[o + j + 64] = vrow[j + 64];
}

// ==================== flash attention on mma.sync tf32 ====================
// BM=128 q-rows per CTA (8 warps x 16 rows), BN=64 keys per step, DH=128.
// Strides (floats): Q/K 132, V 136, P 68 -> all fragment loads bank-conflict-free.
#define AT_QSTR 132
#define AT_KSTR 132
#define AT_VSTR 136
#define AT_PSTR 68
#define AT_SMEM_U32 (128*AT_QSTR + 64*AT_KSTR + 64*AT_VSTR + 128*AT_PSTR)
#define AT_SMEM_BYTES (AT_SMEM_U32 * 4)

__global__ void __launch_bounds__(256) attn_mma_kernel() {
    extern __shared__ uint32_t sm4[];
    uint32_t* Qs = sm4;                          // [128][132] tf32
    uint32_t* Ks = Qs + 128 * AT_QSTR;           // [64][132]  tf32
    uint32_t* Vs = Ks + 64 * AT_KSTR;            // [64][136]  tf32
    uint32_t* Ps = Vs + 64 * AT_VSTR;            // [128][68]  tf32

    int tid  = threadIdx.x;
    int lane = tid & 31;
    int w    = tid >> 5;        // 0..7, owns q rows [w*16, w*16+16)
    int grp  = lane >> 2;       // 0..7
    int tig  = lane & 3;        // 0..3

    int bh = blockIdx.y;
    int b = bh >> 4, h = bh & 15;
    int q0 = blockIdx.x * 128;

    const float* Qg = g_q + (size_t)bh * SS * DHH;
    const float* Kg = g_k + (size_t)bh * SS * DHH;
    const float* Vg = g_v + (size_t)bh * SS * DHH;

    // load Q tile (tf32) once: 128 rows x 128 d
#pragma unroll
    for (int i = 0; i < 16; i++) {
        int flat = tid + i * 256;
        int r = flat >> 5, c = (flat & 31) * 4;
        float4 q4 = *(const float4*)(Qg + (size_t)(q0 + r) * DHH + c);
        uint4 t;
        t.x = f32_to_tf32(q4.x); t.y = f32_to_tf32(q4.y);
        t.z = f32_to_tf32(q4.z); t.w = f32_to_tf32(q4.w);
        *(uint4*)&Qs[r * AT_QSTR + c] = t;
    }

    float o[16][4];
#pragma unroll
    for (int nt = 0; nt < 16; nt++)
#pragma unroll
        for (int i = 0; i < 4; i++) o[nt][i] = 0.f;
    float m0 = -1e30f, m1 = -1e30f, l0 = 0.f, l1 = 0.f;

    int qrow0 = w * 16 + grp;      // rows this thread owns: qrow0, qrow0+8

    for (int kt = 0; kt < SS / 64; kt++) {
        __syncthreads();   // prev iter done reading K (QK) and V (PV)
        // load K,V tile (64 keys x 128 d), convert to tf32
#pragma unroll
        for (int i = 0; i < 8; i++) {
            int flat = tid + i * 256;
            int r = flat >> 5, c = (flat & 31) * 4;
            const float* kp = Kg + (size_t)(kt * 64 + r) * DHH + c;
            float4 k4 = *(const float4*)kp;
            uint4 t;
            t.x = f32_to_tf32(k4.x); t.y = f32_to_tf32(k4.y);
            t.z = f32_to_tf32(k4.z); t.w = f32_to_tf32(k4.w);
            *(uint4*)&Ks[r * AT_KSTR + c] = t;
            float4 v4 = *(const float4*)(Vg + (size_t)(kt * 64 + r) * DHH + c);
            t.x = f32_to_tf32(v4.x); t.y = f32_to_tf32(v4.y);
            t.z = f32_to_tf32(v4.z); t.w = f32_to_tf32(v4.w);
            *(uint4*)&Vs[r * AT_VSTR + c] = t;
        }
        __syncthreads();

        // S = Q K^T : warp-private 16x64 accumulator
        float s[8][4];
#pragma unroll
        for (int nt = 0; nt < 8; nt++)
#pragma unroll
            for (int i = 0; i < 4; i++) s[nt][i] = 0.f;

#pragma unroll
        for (int ks = 0; ks < 16; ks++) {
            uint32_t a0 = Qs[qrow0 * AT_QSTR + ks * 8 + tig];
            uint32_t a1 = Qs[(qrow0 + 8) * AT_QSTR + ks * 8 + tig];
            uint32_t a2 = Qs[qrow0 * AT_QSTR + ks * 8 + tig + 4];
            uint32_t a3 = Qs[(qrow0 + 8) * AT_QSTR + ks * 8 + tig + 4];
#pragma unroll
            for (int nt = 0; nt < 8; nt++) {
                uint32_t b0 = Ks[(nt * 8 + grp) * AT_KSTR + ks * 8 + tig];
                uint32_t b1 = Ks[(nt * 8 + grp) * AT_KSTR + ks * 8 + tig + 4];
                MMA_TF32(s[nt][0], s[nt][1], s[nt][2], s[nt][3], a0, a1, a2, a3, b0, b1);
            }
        }

        // online softmax (rows qrow0 [c0,c1], qrow0+8 [c2,c3])
        float mx0 = -1e30f, mx1 = -1e30f;
#pragma unroll
        for (int nt = 0; nt < 8; nt++) {
            mx0 = fmaxf(mx0, fmaxf(s[nt][0], s[nt][1]));
            mx1 = fmaxf(mx1, fmaxf(s[nt][2], s[nt][3]));
        }
#pragma unroll
        for (int off = 1; off <= 2; off <<= 1) {
            mx0 = fmaxf(mx0, __shfl_xor_sync(0xffffffffu, mx0, off));
            mx1 = fmaxf(mx1, __shfl_xor_sync(0xffffffffu, mx1, off));
        }
        float nm0 = fmaxf(m0, mx0), nm1 = fmaxf(m1, mx1);
        float sc0 = __expf(m0 - nm0), sc1 = __expf(m1 - nm1);
        float ps0 = 0.f, ps1 = 0.f;
#pragma unroll
        for (int nt = 0; nt < 8; nt++) {
            float p0 = __expf(s[nt][0] - nm0);
            float p1 = __expf(s[nt][1] - nm0);
            float p2 = __expf(s[nt][2] - nm1);
            float p3 = __expf(s[nt][3] - nm1);
            ps0 += p0 + p1;
            ps1 += p2 + p3;
            Ps[qrow0 * AT_PSTR + nt * 8 + 2 * tig]       = f32_to_tf32(p0);
            Ps[qrow0 * AT_PSTR + nt * 8 + 2 * tig + 1]   = f32_to_tf32(p1);
            Ps[(qrow0 + 8) * AT_PSTR + nt * 8 + 2 * tig]     = f32_to_tf32(p2);
            Ps[(qrow0 + 8) * AT_PSTR + nt * 8 + 2 * tig + 1] = f32_to_tf32(p3);
        }
#pragma unroll
        for (int off = 1; off <= 2; off <<= 1) {
            ps0 += __shfl_xor_sync(0xffffffffu, ps0, off);
            ps1 += __shfl_xor_sync(0xffffffffu, ps1, off);
        }
        l0 = l0 * sc0 + ps0;  m0 = nm0;
        l1 = l1 * sc1 + ps1;  m1 = nm1;
#pragma unroll
        for (int nt = 0; nt < 16; nt++) {
            o[nt][0] *= sc0; o[nt][1] *= sc0;
            o[nt][2] *= sc1; o[nt][3] *= sc1;
        }
        __syncwarp();   // P rows are warp-private; order stores before loads

        // O += P V : 16 x 128, K=64
#pragma unroll
        for (int ks = 0; ks < 8; ks++) {
            uint32_t a0 = Ps[qrow0 * AT_PSTR + ks * 8 + tig];
            uint32_t a1 = Ps[(qrow0 + 8) * AT_PSTR + ks * 8 + tig];
            uint32_t a2 = Ps[qrow0 * AT_PSTR + ks * 8 + tig + 4];
            uint32_t a3 = Ps[(qrow0 + 8) * AT_PSTR + ks * 8 + tig + 4];
#pragma unroll
            for (int nt = 0; nt < 16; nt++) {
                uint32_t b0 = Vs[(ks * 8 + tig) * AT_VSTR + nt * 8 + grp];
                uint32_t b1 = Vs[(ks * 8 + tig + 4) * AT_VSTR + nt * 8 + grp];
                MMA_TF32(o[nt][0], o[nt][1], o[nt][2], o[nt][3], a0, a1, a2, a3, b0, b1);
            }
        }
    }

    // epilogue: divide by l, write [B,S,H*DH]
    float inv0 = 1.f / l0, inv1 = 1.f / l1;
    int r0 = q0 + qrow0;
    float* dst0 = g_ctx + (size_t)(b * SS + r0) * DD + h * DHH;
    float* dst1 = g_ctx + (size_t)(b * SS + r0 + 8) * DD + h * DHH;
#pragma unroll
    for (int nt = 0; nt < 16; nt++) {
        int cn = nt * 8 + 2 * tig;
        *(float2*)(dst0 + cn) = make_float2(o[nt][0] * inv0, o[nt][1] * inv0);
        *(float2*)(dst1 + cn) = make_float2(o[nt][2] * inv1, o[nt][3] * inv1);
    }
}

// ---------------- launch ----------------
extern "C" void kernel_launch(void* const* d_in, const int* in_sizes, int n_in,
                              void* d_out, int out_size) {
    const float* x    = (const float*)d_in[0];
    const float* Wqkv = (const float*)d_in[1];
    const float* bqkv = (const float*)d_in[2];
    const float* Wo   = (const float*)d_in[3];
    const float* bo   = (const float*)d_in[4];
    float* out = (float*)d_out;

    void *qkvPtr, *ctxPtr;
    cudaGetSymbolAddress(&qkvPtr, g_qkv);
    cudaGetSymbolAddress(&ctxPtr, g_ctx);

    cudaFuncSetAttribute(attn_mma_kernel,
                         cudaFuncAttributeMaxDynamicSharedMemorySize,
                         AT_SMEM_BYTES);

    // 1) RoPE tables
    rope_table_kernel<<<(SS * 64 + 255) / 256, 256>>>();

    // 2) QKV GEMM (tf32 mma.sync)
    mma_gemm_kernel<<<dim3(ND3 / 128, (BB * SS) / 128), 256>>>(
        x, Wqkv, bqkv, (float*)qkvPtr, BB * SS, ND3, DD);

    // 3) RoPE + split/transpose (+ fold 1/sqrt(DH) into Q)
    rope_split_kernel<<<(BB * HH * SS * 64) / 256, 256>>>();

    // 4) flash attention (tf32 mma) -> g_ctx
    attn_mma_kernel<<<dim3(SS / 128, BB * HH), 256, AT_SMEM_BYTES>>>();

    // 5) output projection (tf32 mma.sync)
    mma_gemm_kernel<<<dim3(DD / 128, (BB * SS) / 128), 256>>>(
        (const float*)ctxPtr, Wo, bo, out, BB * SS, DD, DD);
}

// round 6
// speedup vs baseline: 3.3872x; 1.1023x over previous
#include <cuda_runtime.h>
#include <math.h>
#include <stdint.h>

#define BB 2
#define SS 2048
#define DD 2048
#define HH 16
#define DHH 128
#define ND3 (3*DD)

// ---------------- scratch (static device globals; no allocation) ----------------
__device__ float g_qkv[(size_t)BB*SS*ND3];      // [B,S,3D]
__device__ float g_q  [(size_t)BB*HH*SS*DHH];   // [B,H,S,DH] (pre-scaled by 1/sqrt(DH))
__device__ float g_k  [(size_t)BB*HH*SS*DHH];
__device__ float g_v  [(size_t)BB*HH*SS*DHH];
__device__ float g_ctx[(size_t)BB*SS*DD];       // [B,S,H*DH]
__device__ float g_cos[SS*64];
__device__ float g_sin[SS*64];

__device__ __forceinline__ uint32_t f32_to_tf32(float x) {
    uint32_t r;
    asm("cvt.rna.tf32.f32 %0, %1;" : "=r"(r) : "f"(x));
    return r;
}

#define MMA_TF32(c0,c1,c2,c3,a0,a1,a2,a3,b0,b1)                          \
    asm volatile(                                                        \
        "mma.sync.aligned.m16n8k8.row.col.f32.tf32.tf32.f32 "            \
        "{%0,%1,%2,%3}, {%4,%5,%6,%7}, {%8,%9}, {%0,%1,%2,%3};"          \
        : "+f"(c0), "+f"(c1), "+f"(c2), "+f"(c3)                         \
        : "r"(a0), "r"(a1), "r"(a2), "r"(a3), "r"(b0), "r"(b1))

// ==================== tf32 mma.sync GEMM v2 ====================
// CTA tile 256x128, 512 threads = 16 warps (4x4), warp tile 64x32, K-chunk 32.
#define G2_BM 256
#define G2_BN 128
#define G2_BK 32
#define G2_ASTR 36
#define G2_BSTR 132
#define G2_SMEM_BYTES ((G2_BM*G2_ASTR + G2_BK*G2_BSTR) * 4)

__global__ void __launch_bounds__(512) mma_gemm_kernel(
    const float* __restrict__ A, const float* __restrict__ Bm,
    const float* __restrict__ bias, float* __restrict__ C,
    int M, int N, int K)
{
    extern __shared__ uint32_t gsm[];
    uint32_t* As = gsm;                    // [256][36]
    uint32_t* Bs = gsm + G2_BM * G2_ASTR;  // [32][132]

    int tid  = threadIdx.x;
    int lane = tid & 31;
    int w    = tid >> 5;     // 0..15
    int wr   = w >> 2;       // 0..3 (64-row block)
    int wc   = w & 3;        // 0..3 (32-col block)
    int grp  = lane >> 2;
    int tig  = lane & 3;
    int m0 = blockIdx.y * G2_BM;
    int n0 = blockIdx.x * G2_BN;

    float acc[4][4][4];
#pragma unroll
    for (int mt = 0; mt < 4; mt++)
#pragma unroll
        for (int nt = 0; nt < 4; nt++)
#pragma unroll
            for (int i = 0; i < 4; i++) acc[mt][nt][i] = 0.f;

    float4 pa[4], pb[2];
#pragma unroll
    for (int i = 0; i < 4; i++) {
        int s = tid + i * 512;
        int ar = s >> 3, ac = (s & 7) * 4;
        pa[i] = *(const float4*)(A + (size_t)(m0 + ar) * K + ac);
    }
#pragma unroll
    for (int i = 0; i < 2; i++) {
        int s = tid + i * 512;
        int br = s >> 5, bc = (s & 31) * 4;
        pb[i] = *(const float4*)(Bm + (size_t)br * N + n0 + bc);
    }

    const int nCh = K / G2_BK;
    for (int kc = 0; kc < nCh; kc++) {
#pragma unroll
        for (int i = 0; i < 4; i++) {
            int s = tid + i * 512;
            int ar = s >> 3, ac = (s & 7) * 4;
            uint4 t;
            t.x = f32_to_tf32(pa[i].x); t.y = f32_to_tf32(pa[i].y);
            t.z = f32_to_tf32(pa[i].z); t.w = f32_to_tf32(pa[i].w);
            *(uint4*)&As[ar * G2_ASTR + ac] = t;
        }
#pragma unroll
        for (int i = 0; i < 2; i++) {
            int s = tid + i * 512;
            int br = s >> 5, bc = (s & 31) * 4;
            uint4 t;
            t.x = f32_to_tf32(pb[i].x); t.y = f32_to_tf32(pb[i].y);
            t.z = f32_to_tf32(pb[i].z); t.w = f32_to_tf32(pb[i].w);
            *(uint4*)&Bs[br * G2_BSTR + bc] = t;
        }
        __syncthreads();

        if (kc + 1 < nCh) {
            int k0 = (kc + 1) * G2_BK;
#pragma unroll
            for (int i = 0; i < 4; i++) {
                int s = tid + i * 512;
                int ar = s >> 3, ac = (s & 7) * 4;
                pa[i] = *(const float4*)(A + (size_t)(m0 + ar) * K + k0 + ac);
            }
#pragma unroll
            for (int i = 0; i < 2; i++) {
                int s = tid + i * 512;
                int br = s >> 5, bc = (s & 31) * 4;
                pb[i] = *(const float4*)(Bm + (size_t)(k0 + br) * N + n0 + bc);
            }
        }

#pragma unroll
        for (int kk = 0; kk < 4; kk++) {
            uint32_t af[4][4], bf[4][2];
#pragma unroll
            for (int mt = 0; mt < 4; mt++) {
                int r = wr * 64 + mt * 16 + grp;
                int kb = kk * 8 + tig;
                af[mt][0] = As[r * G2_ASTR + kb];
                af[mt][1] = As[(r + 8) * G2_ASTR + kb];
                af[mt][2] = As[r * G2_ASTR + kb + 4];
                af[mt][3] = As[(r + 8) * G2_ASTR + kb + 4];
            }
#pragma unroll
            for (int nt = 0; nt < 4; nt++) {
                int cn = wc * 32 + nt * 8 + grp;
                bf[nt][0] = Bs[(kk * 8 + tig) * G2_BSTR + cn];
                bf[nt][1] = Bs[(kk * 8 + tig + 4) * G2_BSTR + cn];
            }
#pragma unroll
            for (int mt = 0; mt < 4; mt++)
#pragma unroll
                for (int nt = 0; nt < 4; nt++)
                    MMA_TF32(acc[mt][nt][0], acc[mt][nt][1], acc[mt][nt][2], acc[mt][nt][3],
                             af[mt][0], af[mt][1], af[mt][2], af[mt][3],
                             bf[nt][0], bf[nt][1]);
        }
        __syncthreads();
    }

#pragma unroll
    for (int mt = 0; mt < 4; mt++) {
        int r0 = m0 + wr * 64 + mt * 16 + grp;
#pragma unroll
        for (int nt = 0; nt < 4; nt++) {
            int cn = n0 + wc * 32 + nt * 8 + tig * 2;
            float b0 = bias[cn], b1 = bias[cn + 1];
            float2 v0 = make_float2(acc[mt][nt][0] + b0, acc[mt][nt][1] + b1);
            float2 v1 = make_float2(acc[mt][nt][2] + b0, acc[mt][nt][3] + b1);
            *(float2*)(C + (size_t)r0 * N + cn) = v0;
            *(float2*)(C + (size_t)(r0 + 8) * N + cn) = v1;
        }
    }
}

// ---------------- RoPE tables ----------------
__global__ void rope_table_kernel() {
    int idx = blockIdx.x * blockDim.x + threadIdx.x;
    if (idx >= SS * 64) return;
    int t = idx >> 6;
    int j = idx & 63;
    double theta = (double)t * pow(10000.0, -(double)j / 64.0);
    g_cos[idx] = (float)cos(theta);
    g_sin[idx] = (float)sin(theta);
}

// ---------------- RoPE + split + transpose to [B,H,S,DH] ----------------
__global__ void rope_split_kernel() {
    int idx = blockIdx.x * blockDim.x + threadIdx.x;
    if (idx >= BB * HH * SS * 64) return;
    int j = idx & 63;
    int s = (idx >> 6) & (SS - 1);
    int h = (idx >> 17) & (HH - 1);
    int b = idx >> 21;

    const float* qrow = g_qkv + (size_t)(b * SS + s) * ND3 + h * DHH;
    const float* krow = qrow + DD;
    const float* vrow = qrow + 2 * DD;
    float c  = g_cos[s * 64 + j];
    float sn = g_sin[s * 64 + j];
    size_t o = ((size_t)(b * HH + h) * SS + s) * DHH;

    const float qscale = 0.088388347648318447f;  // 1/sqrt(128)

    float u0 = qrow[j], u1 = qrow[j + 64], ue = qrow[2 * j], uo = qrow[2 * j + 1];
    g_q[o + j]      = (u0 * c + uo * sn) * qscale;
    g_q[o + j + 64] = (u1 * c - ue * sn) * qscale;

    u0 = krow[j]; u1 = krow[j + 64]; ue = krow[2 * j]; uo = krow[2 * j + 1];
    g_k[o + j]      = u0 * c + uo * sn;
    g_k[o + j + 64] = u1 * c - ue * sn;

    g_v[o + j]      = vrow[j];
    g_v[o + j + 64] = vrow[j + 64];
}

// ==================== flash attention on mma.sync tf32, 512 threads ====================
// BM=128 q-rows, BN=64 keys/step. 16 warps: warp (g, half); g=row group (16 rows),
// half splits the 64 keys in QK (32 each) and the 128 output cols in PV (64 each).
#define AT_QSTR 132
#define AT_KSTR 132
#define AT_VSTR 136
#define AT_PSTR 68
#define AT_RED  (128*AT_QSTR + 64*AT_KSTR + 64*AT_VSTR + 128*AT_PSTR)
#define AT_SMEM_U32 (AT_RED + 512)
#define AT_SMEM_BYTES (AT_SMEM_U32 * 4)

__global__ void __launch_bounds__(512) attn_mma_kernel() {
    extern __shared__ uint32_t sm4[];
    uint32_t* Qs = sm4;                          // [128][132] tf32
    uint32_t* Ks = Qs + 128 * AT_QSTR;           // [64][132]  tf32
    uint32_t* Vs = Ks + 64 * AT_KSTR;            // [64][136]  tf32
    uint32_t* Ps = Vs + 64 * AT_VSTR;            // [128][68]  tf32
    float* redmax = (float*)(sm4 + AT_RED);      // [2][128]
    float* redsum = redmax + 256;                // [2][128]

    int tid  = threadIdx.x;
    int lane = tid & 31;
    int w    = tid >> 5;        // 0..15
    int g    = w & 7;           // row group: q rows [g*16, g*16+16)
    int half = w >> 3;          // 0/1: key half (QK), out-col half (PV)
    int grp  = lane >> 2;       // 0..7
    int tig  = lane & 3;        // 0..3

    int bh = blockIdx.y;
    int b = bh >> 4, h = bh & 15;
    int q0 = blockIdx.x * 128;

    const float* Qg = g_q + (size_t)bh * SS * DHH;
    const float* Kg = g_k + (size_t)bh * SS * DHH;
    const float* Vg = g_v + (size_t)bh * SS * DHH;

    // load Q tile (tf32): 128 rows x 128 d
#pragma unroll
    for (int i = 0; i < 8; i++) {
        int flat = tid + i * 512;
        int r = flat >> 5, c = (flat & 31) * 4;
        float4 q4 = *(const float4*)(Qg + (size_t)(q0 + r) * DHH + c);
        uint4 t;
        t.x = f32_to_tf32(q4.x); t.y = f32_to_tf32(q4.y);
        t.z = f32_to_tf32(q4.z); t.w = f32_to_tf32(q4.w);
        *(uint4*)&Qs[r * AT_QSTR + c] = t;
    }

    float o[8][4];
#pragma unroll
    for (int nt = 0; nt < 8; nt++)
#pragma unroll
        for (int i = 0; i < 4; i++) o[nt][i] = 0.f;
    float m0 = -1e30f, m1 = -1e30f, l0 = 0.f, l1 = 0.f;

    int qr0 = g * 16 + grp;     // thread's rows: qr0, qr0+8

    for (int kt = 0; kt < SS / 64; kt++) {
        __syncthreads();   // prev iter done with Ks/Vs/Ps
#pragma unroll
        for (int i = 0; i < 4; i++) {
            int flat = tid + i * 512;
            int r = flat >> 5, c = (flat & 31) * 4;
            float4 k4 = *(const float4*)(Kg + (size_t)(kt * 64 + r) * DHH + c);
            uint4 t;
            t.x = f32_to_tf32(k4.x); t.y = f32_to_tf32(k4.y);
            t.z = f32_to_tf32(k4.z); t.w = f32_to_tf32(k4.w);
            *(uint4*)&Ks[r * AT_KSTR + c] = t;
            float4 v4 = *(const float4*)(Vg + (size_t)(kt * 64 + r) * DHH + c);
            t.x = f32_to_tf32(v4.x); t.y = f32_to_tf32(v4.y);
            t.z = f32_to_tf32(v4.z); t.w = f32_to_tf32(v4.w);
            *(uint4*)&Vs[r * AT_VSTR + c] = t;
        }
        __syncthreads();

        // S = Q K^T : warp computes 16 rows x 32 keys (its half)
        float s[4][4];
#pragma unroll
        for (int nt = 0; nt < 4; nt++)
#pragma unroll
            for (int i = 0; i < 4; i++) s[nt][i] = 0.f;

#pragma unroll
        for (int ks = 0; ks < 16; ks++) {
            uint32_t a0 = Qs[qr0 * AT_QSTR + ks * 8 + tig];
            uint32_t a1 = Qs[(qr0 + 8) * AT_QSTR + ks * 8 + tig];
            uint32_t a2 = Qs[qr0 * AT_QSTR + ks * 8 + tig + 4];
            uint32_t a3 = Qs[(qr0 + 8) * AT_QSTR + ks * 8 + tig + 4];
#pragma unroll
            for (int nt = 0; nt < 4; nt++) {
                int kr = half * 32 + nt * 8 + grp;
                uint32_t b0 = Ks[kr * AT_KSTR + ks * 8 + tig];
                uint32_t b1 = Ks[kr * AT_KSTR + ks * 8 + tig + 4];
                MMA_TF32(s[nt][0], s[nt][1], s[nt][2], s[nt][3], a0, a1, a2, a3, b0, b1);
            }
        }

        // partial max over this warp's 32 keys
        float mx0 = -1e30f, mx1 = -1e30f;
#pragma unroll
        for (int nt = 0; nt < 4; nt++) {
            mx0 = fmaxf(mx0, fmaxf(s[nt][0], s[nt][1]));
            mx1 = fmaxf(mx1, fmaxf(s[nt][2], s[nt][3]));
        }
#pragma unroll
        for (int off = 1; off <= 2; off <<= 1) {
            mx0 = fmaxf(mx0, __shfl_xor_sync(0xffffffffu, mx0, off));
            mx1 = fmaxf(mx1, __shfl_xor_sync(0xffffffffu, mx1, off));
        }
        if (tig == 0) {
            redmax[half * 128 + qr0]     = mx0;
            redmax[half * 128 + qr0 + 8] = mx1;
        }
        __syncthreads();
        float nm0 = fmaxf(m0, fmaxf(redmax[qr0], redmax[128 + qr0]));
        float nm1 = fmaxf(m1, fmaxf(redmax[qr0 + 8], redmax[128 + qr0 + 8]));
        float sc0 = __expf(m0 - nm0), sc1 = __expf(m1 - nm1);

        float ps0 = 0.f, ps1 = 0.f;
#pragma unroll
        for (int nt = 0; nt < 4; nt++) {
            float p0 = __expf(s[nt][0] - nm0);
            float p1 = __expf(s[nt][1] - nm0);
            float p2 = __expf(s[nt][2] - nm1);
            float p3 = __expf(s[nt][3] - nm1);
            ps0 += p0 + p1;
            ps1 += p2 + p3;
            int pc = half * 32 + nt * 8 + 2 * tig;
            Ps[qr0 * AT_PSTR + pc]           = f32_to_tf32(p0);
            Ps[qr0 * AT_PSTR + pc + 1]       = f32_to_tf32(p1);
            Ps[(qr0 + 8) * AT_PSTR + pc]     = f32_to_tf32(p2);
            Ps[(qr0 + 8) * AT_PSTR + pc + 1] = f32_to_tf32(p3);
        }
#pragma unroll
        for (int off = 1; off <= 2; off <<= 1) {
            ps0 += __shfl_xor_sync(0xffffffffu, ps0, off);
            ps1 += __shfl_xor_sync(0xffffffffu, ps1, off);
        }
        if (tig == 0) {
            redsum[half * 128 + qr0]     = ps0;
            redsum[half * 128 + qr0 + 8] = ps1;
        }
        __syncthreads();   // P complete (both halves), sums ready
        float pt0 = redsum[qr0] + redsum[128 + qr0];
        float pt1 = redsum[qr0 + 8] + redsum[128 + qr0 + 8];
        l0 = l0 * sc0 + pt0;  m0 = nm0;
        l1 = l1 * sc1 + pt1;  m1 = nm1;
#pragma unroll
        for (int nt = 0; nt < 8; nt++) {
            o[nt][0] *= sc0; o[nt][1] *= sc0;
            o[nt][2] *= sc1; o[nt][3] *= sc1;
        }

        // O += P V : warp computes 16 rows x 64 out cols (its half), K=64 keys
#pragma unroll
        for (int ks = 0; ks < 8; ks++) {
            uint32_t a0 = Ps[qr0 * AT_PSTR + ks * 8 + tig];
            uint32_t a1 = Ps[(qr0 + 8) * AT_PSTR + ks * 8 + tig];
            uint32_t a2 = Ps[qr0 * AT_PSTR + ks * 8 + tig + 4];
            uint32_t a3 = Ps[(qr0 + 8) * AT_PSTR + ks * 8 + tig + 4];
#pragma unroll
            for (int nt = 0; nt < 8; nt++) {
                int vc = half * 64 + nt * 8 + grp;
                uint32_t b0 = Vs[(ks * 8 + tig) * AT_VSTR + vc];
                uint32_t b1 = Vs[(ks * 8 + tig + 4) * AT_VSTR + vc];
                MMA_TF32(o[nt][0], o[nt][1], o[nt][2], o[nt][3], a0, a1, a2, a3, b0, b1);
            }
        }
    }

    // epilogue
    float inv0 = 1.f / l0, inv1 = 1.f / l1;
    int r0 = q0 + qr0;
    float* dst0 = g_ctx + (size_t)(b * SS + r0) * DD + h * DHH + half * 64;
    float* dst1 = g_ctx + (size_t)(b * SS + r0 + 8) * DD + h * DHH + half * 64;
#pragma unroll
    for (int nt = 0; nt < 8; nt++) {
        int cn = nt * 8 + 2 * tig;
        *(float2*)(dst0 + cn) = make_float2(o[nt][0] * inv0, o[nt][1] * inv0);
        *(float2*)(dst1 + cn) = make_float2(o[nt][2] * inv1, o[nt][3] * inv1);
    }
}

// ---------------- launch ----------------
extern "C" void kernel_launch(void* const* d_in, const int* in_sizes, int n_in,
                              void* d_out, int out_size) {
    const float* x    = (const float*)d_in[0];
    const float* Wqkv = (const float*)d_in[1];
    const float* bqkv = (const float*)d_in[2];
    const float* Wo   = (const float*)d_in[3];
    const float* bo   = (const float*)d_in[4];
    float* out = (float*)d_out;

    void *qkvPtr, *ctxPtr;
    cudaGetSymbolAddress(&qkvPtr, g_qkv);
    cudaGetSymbolAddress(&ctxPtr, g_ctx);

    cudaFuncSetAttribute(attn_mma_kernel,
                         cudaFuncAttributeMaxDynamicSharedMemorySize,
                         AT_SMEM_BYTES);
    cudaFuncSetAttribute(mma_gemm_kernel,
                         cudaFuncAttributeMaxDynamicSharedMemorySize,
                         G2_SMEM_BYTES);

    // 1) RoPE tables
    rope_table_kernel<<<(SS * 64 + 255) / 256, 256>>>();

    // 2) QKV GEMM (tf32 mma.sync): [4096,2048] @ [2048,6144] + bqkv
    mma_gemm_kernel<<<dim3(ND3 / G2_BN, (BB * SS) / G2_BM), 512, G2_SMEM_BYTES>>>(
        x, Wqkv, bqkv, (float*)qkvPtr, BB * SS, ND3, DD);

    // 3) RoPE + split/transpose (+ fold 1/sqrt(DH) into Q)
    rope_split_kernel<<<(BB * HH * SS * 64) / 256, 256>>>();

    // 4) flash attention (tf32 mma, 512 thr) -> g_ctx
    attn_mma_kernel<<<dim3(SS / 128, BB * HH), 512, AT_SMEM_BYTES>>>();

    // 5) output projection (tf32 mma.sync)
    mma_gemm_kernel<<<dim3(DD / G2_BN, (BB * SS) / G2_BM), 512, G2_SMEM_BYTES>>>(
        (const float*)ctxPtr, Wo, bo, out, BB * SS, DD, DD);
}